// round 5
// baseline (speedup 1.0000x reference)
#include <cuda_runtime.h>
#include <cuda_fp16.h>
#include <mma.h>
#include <cstdint>

using namespace nvcuda;

#define T_TOK 4096
#define DDIM  768
#define IDIM  2048
#define NEXP  8
#define TM    128
#define NTILES 40            // 4096/128 + 8 (worst-case per-expert padding)
#define PADROWS (NTILES*TM)
#define KC    64
#define LDH   72             // smem leading dim (halves): 144B, 16B-aligned rows
#define LDST  132            // fp32 staging stride: %4==0 (wmma), row %16B==0 (float4)

// ---------------- device-global scratch (no allocation allowed) -------------
__device__ int    g_perm[PADROWS];
__device__ int    g_tile_expert[NTILES];
__device__ __half g_wg[(size_t)NEXP * IDIM * DDIM];
__device__ __half g_wu[(size_t)NEXP * IDIM * DDIM];
__device__ __half g_wd[(size_t)NEXP * DDIM * IDIM];
__device__ __half g_x [(size_t)T_TOK * DDIM];
__device__ __half g_h [(size_t)PADROWS * IDIM];

// ---------------- cp.async helpers ------------------------------------------
__device__ __forceinline__ void cp16(void* smem, const void* gmem) {
    uint32_t s = (uint32_t)__cvta_generic_to_shared(smem);
    asm volatile("cp.async.cg.shared.global [%0], [%1], 16;" :: "r"(s), "l"(gmem));
}
#define CP_COMMIT() asm volatile("cp.async.commit_group;")
#define CP_WAIT1()  asm volatile("cp.async.wait_group 1;")
#define CP_WAIT0()  asm volatile("cp.async.wait_group 0;")

// ---------------------------------------------------------------------------
// fused fp32 -> fp16 conversion of gate_w, up_w, down_w, x
// ---------------------------------------------------------------------------
#define W4 (NEXP * IDIM * DDIM / 4)
#define X4 (T_TOK * DDIM / 4)
__global__ void cvt_all(const float4* __restrict__ gw, const float4* __restrict__ uw,
                        const float4* __restrict__ dw, const float4* __restrict__ x) {
    const int TOT = 3 * W4 + X4;
    int i = blockIdx.x * blockDim.x + threadIdx.x;
    int stride = gridDim.x * blockDim.x;
    for (; i < TOT; i += stride) {
        const float4* src; uint2* dst; int k;
        if (i < W4)          { src = gw; dst = (uint2*)g_wg; k = i; }
        else if (i < 2 * W4) { src = uw; dst = (uint2*)g_wu; k = i - W4; }
        else if (i < 3 * W4) { src = dw; dst = (uint2*)g_wd; k = i - 2 * W4; }
        else                 { src = x;  dst = (uint2*)g_x;  k = i - 3 * W4; }
        float4 v = src[k];
        __half2 a = __floats2half2_rn(v.x, v.y);
        __half2 b = __floats2half2_rn(v.z, v.w);
        uint2 o; o.x = *(uint32_t*)&a; o.y = *(uint32_t*)&b;
        dst[k] = o;
    }
}

// ---------------------------------------------------------------------------
// Routing: counting sort into 128-row-aligned expert groups (int64/int32 safe)
// ---------------------------------------------------------------------------
__global__ void route_kernel(const void* __restrict__ pos) {
    __shared__ int cnt[NEXP], off[NEXP], cur[NEXP];
    __shared__ int s_not64;
    const int tid = threadIdx.x;
    if (tid < NEXP) { cnt[tid] = 0; cur[tid] = 0; }
    if (tid == 0) s_not64 = 0;
    __syncthreads();
    const unsigned long long* pl = (const unsigned long long*)pos;
    for (int i = tid; i < T_TOK / 2; i += blockDim.x)
        if (pl[i] > 7ULL) s_not64 = 1;
    __syncthreads();
    const int is64 = !s_not64;
    const long long* p64 = (const long long*)pos;
    const int*       p32 = (const int*)pos;
    for (int t = tid; t < T_TOK; t += blockDim.x) {
        int e = is64 ? (int)p64[t] : p32[t];
        atomicAdd(&cnt[e], 1);
    }
    for (int i = tid; i < PADROWS; i += blockDim.x) g_perm[i] = -1;
    __syncthreads();
    if (tid == 0) {
        int o = 0;
        for (int e = 0; e < NEXP; e++) {
            off[e] = o;
            int nt = (cnt[e] + TM - 1) / TM;
            for (int k = 0; k < nt; k++) g_tile_expert[o / TM + k] = e;
            o += nt * TM;
        }
        for (int tl = o / TM; tl < NTILES; tl++) g_tile_expert[tl] = -1;
    }
    __syncthreads();
    for (int t = tid; t < T_TOK; t += blockDim.x) {
        int e = is64 ? (int)p64[t] : p32[t];
        int p = off[e] + atomicAdd(&cur[e], 1);
        g_perm[p] = t;
    }
}

// ---------------------------------------------------------------------------
// GEMM1: fused  G|U = X @ [Gw;Uw]^T, 128x128 CTA tile (64 G cols + 64 U cols),
// 4 warps (2x2), warp tile 64x64. B rows per warp-half: [G 0-31 | U 0-31] /
// [G 32-63 | U 32-63] so frag j<2 is G and j>=2 is the matching-column U.
// Epilogue: stage fp32 (G cols 0-63, U cols 64-127), silu(g)*u -> g_h fp16.
// smem: 2 stages x (A 128x72 + B 128x72)*2B = 73728; staging (128x132 fp32) reuses it.
// ---------------------------------------------------------------------------
#define STAGE_BYTES (2 * 128 * LDH * 2)  // A + B, bytes (36864)
__global__ __launch_bounds__(128) void gemm1_kernel() {
    const int tile = blockIdx.x;
    const int e = g_tile_expert[tile];
    if (e < 0) return;
    const int n0 = blockIdx.y * 64;   // column base within each of G, U

    extern __shared__ __half sh[];
    __shared__ int rowtok[128];
    const int tid = threadIdx.x;
    if (tid < 128) rowtok[tid] = g_perm[tile * TM + tid];
    __syncthreads();

    const __half* wg_e = g_wg + (size_t)e * IDIM * DDIM;
    const __half* wu_e = g_wu + (size_t)e * IDIM * DDIM;

    auto load_stage = [&](int s, int k0) {
        __half* A = sh + s * (STAGE_BYTES / 2);
        __half* B = A + 128 * LDH;
#pragma unroll
        for (int j = 0; j < 8; j++) {
            int idx = tid + 128 * j;
            int r = idx >> 3, c = idx & 7;
            int t = rowtok[r]; if (t < 0) t = 0;
            cp16(A + r * LDH + c * 8, g_x + (size_t)t * DDIM + k0 + c * 8);
        }
#pragma unroll
        for (int j = 0; j < 8; j++) {
            int idx = tid + 128 * j;
            int r = idx >> 3, c = idx & 7;
            int q = r & 63;
            int col = n0 + (r >> 6) * 32 + (q & 31);     // weight row index
            const __half* w = (q < 32) ? wg_e : wu_e;
            cp16(B + r * LDH + c * 8, w + (size_t)col * DDIM + k0 + c * 8);
        }
    };

    const int wid = tid >> 5, wm = wid >> 1, wn = wid & 1;

    wmma::fragment<wmma::accumulator, 16, 16, 16, float> acc[4][4];
#pragma unroll
    for (int i = 0; i < 4; i++)
#pragma unroll
        for (int j = 0; j < 4; j++) wmma::fill_fragment(acc[i][j], 0.0f);

    load_stage(0, 0);  CP_COMMIT();
    load_stage(1, KC); CP_COMMIT();

    const int NK = DDIM / KC;  // 12
    for (int kc = 0; kc < NK; kc++) {
        if (kc + 1 < NK) CP_WAIT1(); else CP_WAIT0();
        __syncthreads();
        const int s = kc & 1;
        const __half* A = sh + s * (STAGE_BYTES / 2);
        const __half* B = A + 128 * LDH;
#pragma unroll
        for (int ks = 0; ks < KC / 16; ks++) {
            wmma::fragment<wmma::matrix_a, 16, 16, 16, __half, wmma::row_major> fa[4];
            wmma::fragment<wmma::matrix_b, 16, 16, 16, __half, wmma::col_major> fb[4];
#pragma unroll
            for (int i = 0; i < 4; i++)
                wmma::load_matrix_sync(fa[i], A + (wm * 64 + i * 16) * LDH + ks * 16, LDH);
#pragma unroll
            for (int j = 0; j < 4; j++)
                wmma::load_matrix_sync(fb[j], B + (wn * 64 + j * 16) * LDH + ks * 16, LDH);
#pragma unroll
            for (int i = 0; i < 4; i++)
#pragma unroll
                for (int j = 0; j < 4; j++)
                    wmma::mma_sync(acc[i][j], fa[i], fb[j], acc[i][j]);
        }
        __syncthreads();
        if (kc + 2 < NK) { load_stage(s, (kc + 2) * KC); CP_COMMIT(); }
    }

    // Stage fp32: G frag j<2 -> cols wn*32 + j*16 ; U frag j>=2 -> 64 + wn*32 + (j-2)*16
    float* st = (float*)sh;   // 128 x 132 fp32 = 67584 B <= 73728
    __syncthreads();
#pragma unroll
    for (int i = 0; i < 4; i++)
#pragma unroll
        for (int j = 0; j < 4; j++) {
            int cc = (j < 2) ? (wn * 32 + j * 16) : (64 + wn * 32 + (j - 2) * 16);
            wmma::store_matrix_sync(st + (wm * 64 + i * 16) * LDST + cc,
                                    acc[i][j], LDST, wmma::mem_row_major);
        }
    __syncthreads();

    const size_t rowbase = (size_t)tile * TM;
#pragma unroll
    for (int j = 0; j < 32; j++) {               // 128 rows x 32 half2 cols
        int p = tid + 128 * j;
        int r = p >> 5, c2 = p & 31;
        float g0 = st[r * LDST + c2 * 2];
        float g1 = st[r * LDST + c2 * 2 + 1];
        float u0 = st[r * LDST + 64 + c2 * 2];
        float u1 = st[r * LDST + 64 + c2 * 2 + 1];
        float h0 = (g0 / (1.0f + __expf(-g0))) * u0;
        float h1 = (g1 / (1.0f + __expf(-g1))) * u1;
        __half2 hv = __floats2half2_rn(h0, h1);
        *(uint32_t*)(g_h + (rowbase + r) * IDIM + n0 + c2 * 2) = *(uint32_t*)&hv;
    }
}

// ---------------------------------------------------------------------------
// GEMM2: Out = H @ Dw^T, 128x128 CTA tile, 4 warps (2x2), warp tile 64x64.
// ---------------------------------------------------------------------------
__global__ __launch_bounds__(128) void gemm2_kernel(float* __restrict__ out) {
    const int tile = blockIdx.x;
    const int e = g_tile_expert[tile];
    if (e < 0) return;
    const int n0 = blockIdx.y * 128;

    extern __shared__ __half sh[];
    __shared__ int rowtok[128];
    const int tid = threadIdx.x;
    if (tid < 128) rowtok[tid] = g_perm[tile * TM + tid];
    __syncthreads();

    const __half* wd_p  = g_wd + ((size_t)e * DDIM + n0) * IDIM;
    const __half* hbase = g_h + (size_t)tile * TM * IDIM;

    auto load_stage = [&](int s, int k0) {
        __half* A = sh + s * (STAGE_BYTES / 2);
        __half* B = A + 128 * LDH;
#pragma unroll
        for (int j = 0; j < 8; j++) {
            int idx = tid + 128 * j;
            int r = idx >> 3, c = idx & 7;
            cp16(A + r * LDH + c * 8, hbase + (size_t)r * IDIM + k0 + c * 8);
        }
#pragma unroll
        for (int j = 0; j < 8; j++) {
            int idx = tid + 128 * j;
            int r = idx >> 3, c = idx & 7;
            cp16(B + r * LDH + c * 8, wd_p + (size_t)r * IDIM + k0 + c * 8);
        }
    };

    const int wid = tid >> 5, wm = wid >> 1, wn = wid & 1;

    wmma::fragment<wmma::accumulator, 16, 16, 16, float> acc[4][4];
#pragma unroll
    for (int i = 0; i < 4; i++)
#pragma unroll
        for (int j = 0; j < 4; j++) wmma::fill_fragment(acc[i][j], 0.0f);

    load_stage(0, 0);  CP_COMMIT();
    load_stage(1, KC); CP_COMMIT();

    const int NK = IDIM / KC;  // 32
    for (int kc = 0; kc < NK; kc++) {
        if (kc + 1 < NK) CP_WAIT1(); else CP_WAIT0();
        __syncthreads();
        const int s = kc & 1;
        const __half* A = sh + s * (STAGE_BYTES / 2);
        const __half* B = A + 128 * LDH;
#pragma unroll
        for (int ks = 0; ks < KC / 16; ks++) {
            wmma::fragment<wmma::matrix_a, 16, 16, 16, __half, wmma::row_major> fa[4];
            wmma::fragment<wmma::matrix_b, 16, 16, 16, __half, wmma::col_major> fb[4];
#pragma unroll
            for (int i = 0; i < 4; i++)
                wmma::load_matrix_sync(fa[i], A + (wm * 64 + i * 16) * LDH + ks * 16, LDH);
#pragma unroll
            for (int j = 0; j < 4; j++)
                wmma::load_matrix_sync(fb[j], B + (wn * 64 + j * 16) * LDH + ks * 16, LDH);
#pragma unroll
            for (int i = 0; i < 4; i++)
#pragma unroll
                for (int j = 0; j < 4; j++)
                    wmma::mma_sync(acc[i][j], fa[i], fb[j], acc[i][j]);
        }
        __syncthreads();
        if (kc + 2 < NK) { load_stage(s, (kc + 2) * KC); CP_COMMIT(); }
    }

    // Stage fp32 result (128 x 132), scatter valid rows (float4).
    float* st = (float*)sh;
    __syncthreads();
#pragma unroll
    for (int i = 0; i < 4; i++)
#pragma unroll
        for (int j = 0; j < 4; j++)
            wmma::store_matrix_sync(st + (wm * 64 + i * 16) * LDST + wn * 64 + j * 16,
                                    acc[i][j], LDST, wmma::mem_row_major);
    __syncthreads();
#pragma unroll
    for (int j = 0; j < 32; j++) {               // 128 rows x 32 float4 cols
        int p = tid + 128 * j;
        int r = p >> 5, c4 = (p & 31) * 4;
        int t = rowtok[r];
        if (t >= 0)
            *(float4*)(out + (size_t)t * DDIM + n0 + c4) = *(float4*)&st[r * LDST + c4];
    }
}

// ---------------------------------------------------------------------------
extern "C" void kernel_launch(void* const* d_in, const int* in_sizes, int n_in,
                              void* d_out, int out_size) {
    const float* x   = (const float*)d_in[0];
    const void*  pos = d_in[1];
    // d_in[2] = behavior_index: unused
    const float* gw  = (const float*)d_in[3];
    const float* uw  = (const float*)d_in[4];
    const float* dw  = (const float*)d_in[5];
    float* out = (float*)d_out;

    const int SMEM = 2 * STAGE_BYTES;  // 73728
    cudaFuncSetAttribute(gemm1_kernel, cudaFuncAttributeMaxDynamicSharedMemorySize, SMEM);
    cudaFuncSetAttribute(gemm2_kernel, cudaFuncAttributeMaxDynamicSharedMemorySize, SMEM);

    cvt_all<<<8192, 256>>>((const float4*)gw, (const float4*)uw,
                           (const float4*)dw, (const float4*)x);
    route_kernel<<<1, 256>>>(pos);
    gemm1_kernel<<<dim3(NTILES, IDIM / 64), 128, SMEM>>>();
    gemm2_kernel<<<dim3(NTILES, DDIM / 128), 128, SMEM>>>(out);
}

// round 6
// speedup vs baseline: 1.0185x; 1.0185x over previous
#include <cuda_runtime.h>
#include <cuda_fp16.h>
#include <mma.h>
#include <cstdint>

using namespace nvcuda;

#define T_TOK 4096
#define DDIM  768
#define IDIM  2048
#define NEXP  8
#define TM    128
#define NTILES 40            // 4096/128 + 8 (worst-case per-expert padding)
#define PADROWS (NTILES*TM)
#define KC    64
#define LDH   72             // smem leading dim (halves): 144B, 16B-aligned rows
#define LDST  132            // fp32 staging stride: %4==0 (wmma), row %16B==0 (float4)
#define STAGE_BYTES (2 * 128 * LDH * 2)  // A + B tiles per stage, bytes (36864)

// ---------------- device-global scratch (no allocation allowed) -------------
__device__ int    g_perm[PADROWS];
__device__ int    g_tile_expert[NTILES];
__device__ __half g_wg[(size_t)NEXP * IDIM * DDIM];
__device__ __half g_wu[(size_t)NEXP * IDIM * DDIM];
__device__ __half g_wd[(size_t)NEXP * DDIM * IDIM];
__device__ __half g_x [(size_t)T_TOK * DDIM];
__device__ __half g_h [(size_t)PADROWS * IDIM];

// ---------------- cp.async helpers ------------------------------------------
__device__ __forceinline__ void cp16(void* smem, const void* gmem) {
    uint32_t s = (uint32_t)__cvta_generic_to_shared(smem);
    asm volatile("cp.async.cg.shared.global [%0], [%1], 16;" :: "r"(s), "l"(gmem));
}
#define CP_COMMIT() asm volatile("cp.async.commit_group;")
#define CP_WAIT1()  asm volatile("cp.async.wait_group 1;")
#define CP_WAIT0()  asm volatile("cp.async.wait_group 0;")

// ---------------------------------------------------------------------------
// fused fp32 -> fp16 conversion of gate_w, up_w, down_w, x
// ---------------------------------------------------------------------------
#define W4 (NEXP * IDIM * DDIM / 4)
#define X4 (T_TOK * DDIM / 4)
__global__ void cvt_all(const float4* __restrict__ gw, const float4* __restrict__ uw,
                        const float4* __restrict__ dw, const float4* __restrict__ x) {
    const int TOT = 3 * W4 + X4;
    int i = blockIdx.x * blockDim.x + threadIdx.x;
    int stride = gridDim.x * blockDim.x;
    for (; i < TOT; i += stride) {
        const float4* src; uint2* dst; int k;
        if (i < W4)          { src = gw; dst = (uint2*)g_wg; k = i; }
        else if (i < 2 * W4) { src = uw; dst = (uint2*)g_wu; k = i - W4; }
        else if (i < 3 * W4) { src = dw; dst = (uint2*)g_wd; k = i - 2 * W4; }
        else                 { src = x;  dst = (uint2*)g_x;  k = i - 3 * W4; }
        float4 v = src[k];
        __half2 a = __floats2half2_rn(v.x, v.y);
        __half2 b = __floats2half2_rn(v.z, v.w);
        uint2 o; o.x = *(uint32_t*)&a; o.y = *(uint32_t*)&b;
        dst[k] = o;
    }
}

// ---------------------------------------------------------------------------
// Routing: counting sort into 128-row-aligned expert groups (int64/int32 safe)
// ---------------------------------------------------------------------------
__global__ void route_kernel(const void* __restrict__ pos) {
    __shared__ int cnt[NEXP], off[NEXP], cur[NEXP];
    __shared__ int s_not64;
    const int tid = threadIdx.x;
    if (tid < NEXP) { cnt[tid] = 0; cur[tid] = 0; }
    if (tid == 0) s_not64 = 0;
    __syncthreads();
    const unsigned long long* pl = (const unsigned long long*)pos;
    for (int i = tid; i < T_TOK / 2; i += blockDim.x)
        if (pl[i] > 7ULL) s_not64 = 1;
    __syncthreads();
    const int is64 = !s_not64;
    const long long* p64 = (const long long*)pos;
    const int*       p32 = (const int*)pos;
    for (int t = tid; t < T_TOK; t += blockDim.x) {
        int e = is64 ? (int)p64[t] : p32[t];
        atomicAdd(&cnt[e], 1);
    }
    for (int i = tid; i < PADROWS; i += blockDim.x) g_perm[i] = -1;
    __syncthreads();
    if (tid == 0) {
        int o = 0;
        for (int e = 0; e < NEXP; e++) {
            off[e] = o;
            int nt = (cnt[e] + TM - 1) / TM;
            for (int k = 0; k < nt; k++) g_tile_expert[o / TM + k] = e;
            o += nt * TM;
        }
        for (int tl = o / TM; tl < NTILES; tl++) g_tile_expert[tl] = -1;
    }
    __syncthreads();
    for (int t = tid; t < T_TOK; t += blockDim.x) {
        int e = is64 ? (int)p64[t] : p32[t];
        int p = off[e] + atomicAdd(&cur[e], 1);
        g_perm[p] = t;
    }
}

// ---------------------------------------------------------------------------
// GEMM1: fused  G|U = X @ [Gw;Uw]^T, 128x128 CTA tile (64 G cols + 64 U cols),
// 8 warps (4x2), warp tile 32x64. B rows per warp col-group:
// wn=0: [G 0-31 | U 0-31], wn=1: [G 32-63 | U 32-63] -> frag j<2 = G, j>=2 = U.
// Epilogue: stage fp32 (G cols 0-63, U cols 64-127), silu(g)*u -> g_h fp16.
// ---------------------------------------------------------------------------
__global__ __launch_bounds__(256, 2) void gemm1_kernel() {
    const int tile = blockIdx.x;
    const int e = g_tile_expert[tile];
    if (e < 0) return;
    const int n0 = blockIdx.y * 64;   // column base within each of G, U

    extern __shared__ __half sh[];
    __shared__ int rowtok[128];
    const int tid = threadIdx.x;
    if (tid < 128) rowtok[tid] = g_perm[tile * TM + tid];
    __syncthreads();

    const __half* wg_e = g_wg + (size_t)e * IDIM * DDIM;
    const __half* wu_e = g_wu + (size_t)e * IDIM * DDIM;

    auto load_stage = [&](int s, int k0) {
        __half* A = sh + s * (STAGE_BYTES / 2);
        __half* B = A + 128 * LDH;
#pragma unroll
        for (int j = 0; j < 4; j++) {
            int idx = tid + 256 * j;
            int r = idx >> 3, c = idx & 7;
            int t = rowtok[r]; if (t < 0) t = 0;
            cp16(A + r * LDH + c * 8, g_x + (size_t)t * DDIM + k0 + c * 8);
        }
#pragma unroll
        for (int j = 0; j < 4; j++) {
            int idx = tid + 256 * j;
            int r = idx >> 3, c = idx & 7;
            int q = r & 63;
            int col = n0 + (r >> 6) * 32 + (q & 31);     // weight row index
            const __half* w = (q < 32) ? wg_e : wu_e;
            cp16(B + r * LDH + c * 8, w + (size_t)col * DDIM + k0 + c * 8);
        }
    };

    const int wid = tid >> 5, wm = wid >> 1, wn = wid & 1;

    wmma::fragment<wmma::accumulator, 16, 16, 16, float> acc[2][4];
#pragma unroll
    for (int i = 0; i < 2; i++)
#pragma unroll
        for (int j = 0; j < 4; j++) wmma::fill_fragment(acc[i][j], 0.0f);

    load_stage(0, 0);  CP_COMMIT();
    load_stage(1, KC); CP_COMMIT();

    const int NK = DDIM / KC;  // 12
    for (int kc = 0; kc < NK; kc++) {
        if (kc + 1 < NK) CP_WAIT1(); else CP_WAIT0();
        __syncthreads();
        const int s = kc & 1;
        const __half* A = sh + s * (STAGE_BYTES / 2);
        const __half* B = A + 128 * LDH;
#pragma unroll
        for (int ks = 0; ks < KC / 16; ks++) {
            wmma::fragment<wmma::matrix_a, 16, 16, 16, __half, wmma::row_major> fa[2];
            wmma::fragment<wmma::matrix_b, 16, 16, 16, __half, wmma::col_major> fb[4];
#pragma unroll
            for (int i = 0; i < 2; i++)
                wmma::load_matrix_sync(fa[i], A + (wm * 32 + i * 16) * LDH + ks * 16, LDH);
#pragma unroll
            for (int j = 0; j < 4; j++)
                wmma::load_matrix_sync(fb[j], B + (wn * 64 + j * 16) * LDH + ks * 16, LDH);
#pragma unroll
            for (int i = 0; i < 2; i++)
#pragma unroll
                for (int j = 0; j < 4; j++)
                    wmma::mma_sync(acc[i][j], fa[i], fb[j], acc[i][j]);
        }
        __syncthreads();
        if (kc + 2 < NK) { load_stage(s, (kc + 2) * KC); CP_COMMIT(); }
    }

    // Stage fp32: G frag j<2 -> cols wn*32 + j*16 ; U frag j>=2 -> 64 + wn*32 + (j-2)*16
    float* st = (float*)sh;   // 128 x 132 fp32 = 67584 B <= 73728
    __syncthreads();
#pragma unroll
    for (int i = 0; i < 2; i++)
#pragma unroll
        for (int j = 0; j < 4; j++) {
            int cc = (j < 2) ? (wn * 32 + j * 16) : (64 + wn * 32 + (j - 2) * 16);
            wmma::store_matrix_sync(st + (wm * 32 + i * 16) * LDST + cc,
                                    acc[i][j], LDST, wmma::mem_row_major);
        }
    __syncthreads();

    const size_t rowbase = (size_t)tile * TM;
#pragma unroll
    for (int j = 0; j < 16; j++) {               // 128 rows x 32 half2 cols
        int p = tid + 256 * j;
        int r = p >> 5, c2 = p & 31;
        float g0 = st[r * LDST + c2 * 2];
        float g1 = st[r * LDST + c2 * 2 + 1];
        float u0 = st[r * LDST + 64 + c2 * 2];
        float u1 = st[r * LDST + 64 + c2 * 2 + 1];
        float h0 = (g0 / (1.0f + __expf(-g0))) * u0;
        float h1 = (g1 / (1.0f + __expf(-g1))) * u1;
        __half2 hv = __floats2half2_rn(h0, h1);
        *(uint32_t*)(g_h + (rowbase + r) * IDIM + n0 + c2 * 2) = *(uint32_t*)&hv;
    }
}

// ---------------------------------------------------------------------------
// GEMM2: Out = H @ Dw^T, 128x128 CTA tile, 8 warps (4x2), warp tile 32x64.
// ---------------------------------------------------------------------------
__global__ __launch_bounds__(256, 2) void gemm2_kernel(float* __restrict__ out) {
    const int tile = blockIdx.x;
    const int e = g_tile_expert[tile];
    if (e < 0) return;
    const int n0 = blockIdx.y * 128;

    extern __shared__ __half sh[];
    __shared__ int rowtok[128];
    const int tid = threadIdx.x;
    if (tid < 128) rowtok[tid] = g_perm[tile * TM + tid];
    __syncthreads();

    const __half* wd_p  = g_wd + ((size_t)e * DDIM + n0) * IDIM;
    const __half* hbase = g_h + (size_t)tile * TM * IDIM;

    auto load_stage = [&](int s, int k0) {
        __half* A = sh + s * (STAGE_BYTES / 2);
        __half* B = A + 128 * LDH;
#pragma unroll
        for (int j = 0; j < 4; j++) {
            int idx = tid + 256 * j;
            int r = idx >> 3, c = idx & 7;
            cp16(A + r * LDH + c * 8, hbase + (size_t)r * IDIM + k0 + c * 8);
        }
#pragma unroll
        for (int j = 0; j < 4; j++) {
            int idx = tid + 256 * j;
            int r = idx >> 3, c = idx & 7;
            cp16(B + r * LDH + c * 8, wd_p + (size_t)r * IDIM + k0 + c * 8);
        }
    };

    const int wid = tid >> 5, wm = wid >> 1, wn = wid & 1;

    wmma::fragment<wmma::accumulator, 16, 16, 16, float> acc[2][4];
#pragma unroll
    for (int i = 0; i < 2; i++)
#pragma unroll
        for (int j = 0; j < 4; j++) wmma::fill_fragment(acc[i][j], 0.0f);

    load_stage(0, 0);  CP_COMMIT();
    load_stage(1, KC); CP_COMMIT();

    const int NK = IDIM / KC;  // 32
    for (int kc = 0; kc < NK; kc++) {
        if (kc + 1 < NK) CP_WAIT1(); else CP_WAIT0();
        __syncthreads();
        const int s = kc & 1;
        const __half* A = sh + s * (STAGE_BYTES / 2);
        const __half* B = A + 128 * LDH;
#pragma unroll
        for (int ks = 0; ks < KC / 16; ks++) {
            wmma::fragment<wmma::matrix_a, 16, 16, 16, __half, wmma::row_major> fa[2];
            wmma::fragment<wmma::matrix_b, 16, 16, 16, __half, wmma::col_major> fb[4];
#pragma unroll
            for (int i = 0; i < 2; i++)
                wmma::load_matrix_sync(fa[i], A + (wm * 32 + i * 16) * LDH + ks * 16, LDH);
#pragma unroll
            for (int j = 0; j < 4; j++)
                wmma::load_matrix_sync(fb[j], B + (wn * 64 + j * 16) * LDH + ks * 16, LDH);
#pragma unroll
            for (int i = 0; i < 2; i++)
#pragma unroll
                for (int j = 0; j < 4; j++)
                    wmma::mma_sync(acc[i][j], fa[i], fb[j], acc[i][j]);
        }
        __syncthreads();
        if (kc + 2 < NK) { load_stage(s, (kc + 2) * KC); CP_COMMIT(); }
    }

    // Stage fp32 result (128 x 132), scatter valid rows (float4).
    float* st = (float*)sh;
    __syncthreads();
#pragma unroll
    for (int i = 0; i < 2; i++)
#pragma unroll
        for (int j = 0; j < 4; j++)
            wmma::store_matrix_sync(st + (wm * 32 + i * 16) * LDST + wn * 64 + j * 16,
                                    acc[i][j], LDST, wmma::mem_row_major);
    __syncthreads();
#pragma unroll
    for (int j = 0; j < 16; j++) {               // 128 rows x 32 float4 cols
        int p = tid + 256 * j;
        int r = p >> 5, c4 = (p & 31) * 4;
        int t = rowtok[r];
        if (t >= 0)
            *(float4*)(out + (size_t)t * DDIM + n0 + c4) = *(float4*)&st[r * LDST + c4];
    }
}

// ---------------------------------------------------------------------------
extern "C" void kernel_launch(void* const* d_in, const int* in_sizes, int n_in,
                              void* d_out, int out_size) {
    const float* x   = (const float*)d_in[0];
    const void*  pos = d_in[1];
    // d_in[2] = behavior_index: unused
    const float* gw  = (const float*)d_in[3];
    const float* uw  = (const float*)d_in[4];
    const float* dw  = (const float*)d_in[5];
    float* out = (float*)d_out;

    const int SMEM = 2 * STAGE_BYTES;  // 73728
    cudaFuncSetAttribute(gemm1_kernel, cudaFuncAttributeMaxDynamicSharedMemorySize, SMEM);
    cudaFuncSetAttribute(gemm2_kernel, cudaFuncAttributeMaxDynamicSharedMemorySize, SMEM);

    cvt_all<<<8192, 256>>>((const float4*)gw, (const float4*)uw,
                           (const float4*)dw, (const float4*)x);
    route_kernel<<<1, 256>>>(pos);
    gemm1_kernel<<<dim3(NTILES, IDIM / 64), 256, SMEM>>>();
    gemm2_kernel<<<dim3(NTILES, DDIM / 128), 256, SMEM>>>(out);
}

// round 7
// speedup vs baseline: 1.2089x; 1.1869x over previous
#include <cuda_runtime.h>
#include <cuda_fp16.h>
#include <mma.h>
#include <cstdint>

using namespace nvcuda;

#define T_TOK 4096
#define DDIM  768
#define IDIM  2048
#define NEXP  8
#define TM    128
#define NTILES 40            // 4096/128 + 8 (worst-case per-expert padding)
#define PADROWS (NTILES*TM)
#define KC    64             // halves per K chunk
#define LDH   72             // padded row length (halves): 144B rows, conflict-free ldmatrix
#define LDST  132            // fp32 staging stride: %4==0 (wmma), row %16B==0 (float4)
#define TILE_BYTES (128 * LDH * 2)       // one A or B stage tile: 18432 B, contiguous
#define STAGE_BYTES (2 * TILE_BYTES)     // A + B: 36864 B
#define NSTAGE 3
#define GSMEM (NSTAGE * STAGE_BYTES)     // 110592 B

// ---------------- device-global scratch (tiled layouts, no allocation) ------
__device__ int    g_perm[PADROWS];
__device__ int    g_tile_expert[NTILES];
// [e][y:32][kc:12][r:128][72]  rows pre-interleaved [G0-31|U0-31|G32-63|U32-63]
__device__ __half g_wgu[(size_t)NEXP * 32 * 12 * 128 * LDH];
// [e][y:6][kc:32][r:128][72]
__device__ __half g_wdt[(size_t)NEXP * 6 * 32 * 128 * LDH];
// [tile:40][kc:12][r:128][72]  rows already permuted (pad rows = 0)
__device__ __half g_xt [(size_t)NTILES * 12 * 128 * LDH];
// [tile:40][kc:32][r:128][72]  gemm1 colblock y == gemm2 kchunk y
__device__ __half g_ht [(size_t)NTILES * 32 * 128 * LDH];

// ---------------- PTX helpers -----------------------------------------------
__device__ __forceinline__ uint32_t smem_u32(const void* p) {
    uint32_t a;
    asm("{ .reg .u64 t; cvta.to.shared.u64 t, %1; cvt.u32.u64 %0, t; }" : "=r"(a) : "l"(p));
    return a;
}
__device__ __forceinline__ void mbar_init(uint32_t a) {
    asm volatile("mbarrier.init.shared.b64 [%0], 1;" :: "r"(a) : "memory");
}
__device__ __forceinline__ void mbar_expect_tx(uint32_t a, uint32_t bytes) {
    asm volatile("mbarrier.arrive.expect_tx.shared.b64 _, [%0], %1;" :: "r"(a), "r"(bytes) : "memory");
}
__device__ __forceinline__ void mbar_wait(uint32_t mbar, int parity) {
    asm volatile(
        "{\n\t.reg .pred P;\n\t"
        "WL_%=:\n\t"
        "mbarrier.try_wait.parity.acquire.cta.shared::cta.b64 P, [%0], %1, 0x989680;\n\t"
        "@P bra.uni WD_%=;\n\t"
        "bra.uni WL_%=;\n\t"
        "WD_%=:\n\t}"
        :: "r"(mbar), "r"(parity) : "memory");
}
__device__ __forceinline__ void bulk_g2s(uint32_t dst, const void* src, uint32_t bytes, uint32_t mbar) {
    asm volatile(
        "cp.async.bulk.shared::cluster.global.mbarrier::complete_tx::bytes [%0], [%1], %2, [%3];"
        :: "r"(dst), "l"(src), "r"(bytes), "r"(mbar) : "memory");
}
#define FENCE_ASYNC() asm volatile("fence.proxy.async.shared::cta;" ::: "memory")

// ---------------------------------------------------------------------------
// Routing: counting sort into 128-row-aligned expert groups (int64/int32 safe)
// ---------------------------------------------------------------------------
__global__ void route_kernel(const void* __restrict__ pos) {
    __shared__ int cnt[NEXP], off[NEXP], cur[NEXP];
    __shared__ int s_not64;
    const int tid = threadIdx.x;
    if (tid < NEXP) { cnt[tid] = 0; cur[tid] = 0; }
    if (tid == 0) s_not64 = 0;
    __syncthreads();
    const unsigned long long* pl = (const unsigned long long*)pos;
    for (int i = tid; i < T_TOK / 2; i += blockDim.x)
        if (pl[i] > 7ULL) s_not64 = 1;
    __syncthreads();
    const int is64 = !s_not64;
    const long long* p64 = (const long long*)pos;
    const int*       p32 = (const int*)pos;
    for (int t = tid; t < T_TOK; t += blockDim.x) {
        int e = is64 ? (int)p64[t] : p32[t];
        atomicAdd(&cnt[e], 1);
    }
    for (int i = tid; i < PADROWS; i += blockDim.x) g_perm[i] = -1;
    __syncthreads();
    if (tid == 0) {
        int o = 0;
        for (int e = 0; e < NEXP; e++) {
            off[e] = o;
            int nt = (cnt[e] + TM - 1) / TM;
            for (int k = 0; k < nt; k++) g_tile_expert[o / TM + k] = e;
            o += nt * TM;
        }
        for (int tl = o / TM; tl < NTILES; tl++) g_tile_expert[tl] = -1;
    }
    __syncthreads();
    for (int t = tid; t < T_TOK; t += blockDim.x) {
        int e = is64 ? (int)p64[t] : p32[t];
        int p = off[e] + atomicAdd(&cur[e], 1);
        g_perm[p] = t;
    }
}

// ---------------------------------------------------------------------------
// cvt: fp32 -> fp16 into tiled layouts. dst offset == idx*8 halves by design
// (index decomposition matches layout order, c8 fastest).
// ---------------------------------------------------------------------------
__device__ __forceinline__ uint4 cvt8(const float* src) {
    float4 v0 = *(const float4*)src;
    float4 v1 = *(const float4*)(src + 4);
    __half2 h0 = __floats2half2_rn(v0.x, v0.y), h1 = __floats2half2_rn(v0.z, v0.w);
    __half2 h2 = __floats2half2_rn(v1.x, v1.y), h3 = __floats2half2_rn(v1.z, v1.w);
    uint4 o;
    o.x = *(uint32_t*)&h0; o.y = *(uint32_t*)&h1;
    o.z = *(uint32_t*)&h2; o.w = *(uint32_t*)&h3;
    return o;
}

__global__ void cvt_wgu(const float* __restrict__ gw, const float* __restrict__ uw) {
    const int TOT = NEXP * 32 * 12 * 128 * 9;
    int idx = blockIdx.x * 256 + threadIdx.x;
    if (idx >= TOT) return;
    int c8 = idx % 9; int t1 = idx / 9;
    int r  = t1 % 128; t1 /= 128;
    int kc = t1 % 12;  t1 /= 12;
    int y  = t1 % 32;  int e = t1 / 32;
    uint4 o = make_uint4(0, 0, 0, 0);
    if (c8 < 8) {
        int q = r & 63;
        int wrow = y * 64 + (r >> 6) * 32 + (q & 31);
        const float* src = ((q < 32) ? gw : uw) + ((size_t)e * IDIM + wrow) * DDIM + kc * 64 + c8 * 8;
        o = cvt8(src);
    }
    *(uint4*)(g_wgu + (size_t)idx * 8) = o;
}

__global__ void cvt_wd(const float* __restrict__ dw) {
    const int TOT = NEXP * 6 * 32 * 128 * 9;
    int idx = blockIdx.x * 256 + threadIdx.x;
    if (idx >= TOT) return;
    int c8 = idx % 9; int t1 = idx / 9;
    int r  = t1 % 128; t1 /= 128;
    int kc = t1 % 32;  t1 /= 32;
    int y  = t1 % 6;   int e = t1 / 6;
    uint4 o = make_uint4(0, 0, 0, 0);
    if (c8 < 8) {
        const float* src = dw + ((size_t)e * DDIM + y * 128 + r) * IDIM + kc * 64 + c8 * 8;
        o = cvt8(src);
    }
    *(uint4*)(g_wdt + (size_t)idx * 8) = o;
}

__global__ void cvt_x(const float* __restrict__ x) {   // run AFTER route
    const int TOT = NTILES * 12 * 128 * 9;
    int idx = blockIdx.x * 256 + threadIdx.x;
    if (idx >= TOT) return;
    int c8 = idx % 9; int t1 = idx / 9;
    int r  = t1 % 128; t1 /= 128;
    int kc = t1 % 12;  int tile = t1 / 12;
    uint4 o = make_uint4(0, 0, 0, 0);
    int t = g_perm[tile * TM + r];
    if (c8 < 8 && t >= 0)
        o = cvt8(x + (size_t)t * DDIM + kc * 64 + c8 * 8);
    *(uint4*)(g_xt + (size_t)idx * 8) = o;
}

// ---------------------------------------------------------------------------
// GEMM1: G|U = X @ [Gw;Uw]^T, 128x128 CTA tile, 8 warps (4x2), warp 32x64.
// Loads: one bulk copy per A/B tile per stage (18432 B each), 3 stages.
// Epilogue: silu(g)*u -> g_ht[tile][y][r][c] (tiled for gemm2).
// ---------------------------------------------------------------------------
__global__ __launch_bounds__(256, 2) __cluster_dims__(1, 1, 1) void gemm1_kernel() {
    const int tile = blockIdx.x;
    const int e = g_tile_expert[tile];
    if (e < 0) return;
    const int y = blockIdx.y;          // colblock of 64 (== gemm2 k-chunk)

    extern __shared__ __align__(128) char sh[];
    __shared__ __align__(8) unsigned long long mbars[NSTAGE];
    const uint32_t sb = smem_u32(sh);
    const uint32_t mb0 = smem_u32(mbars);
    const int tid = threadIdx.x;

    if (tid == 0) {
        for (int s = 0; s < NSTAGE; s++) mbar_init(mb0 + 8 * s);
    }
    __syncthreads();

    const __half* Asrc = g_xt  + (size_t)tile * 12 * 128 * LDH;
    const __half* Bsrc = g_wgu + (size_t)((e * 32 + y) * 12) * 128 * LDH;

    const int NK = DDIM / KC;  // 12
    if (tid == 0) {
        FENCE_ASYNC();
#pragma unroll
        for (int s = 0; s < NSTAGE; s++) {
            mbar_expect_tx(mb0 + 8 * s, STAGE_BYTES);
            bulk_g2s(sb + s * STAGE_BYTES,              Asrc + (size_t)s * 128 * LDH, TILE_BYTES, mb0 + 8 * s);
            bulk_g2s(sb + s * STAGE_BYTES + TILE_BYTES, Bsrc + (size_t)s * 128 * LDH, TILE_BYTES, mb0 + 8 * s);
        }
    }

    const int wid = tid >> 5, wm = wid >> 1, wn = wid & 1;
    wmma::fragment<wmma::accumulator, 16, 16, 16, float> acc[2][4];
#pragma unroll
    for (int i = 0; i < 2; i++)
#pragma unroll
        for (int j = 0; j < 4; j++) wmma::fill_fragment(acc[i][j], 0.0f);

    for (int kc = 0; kc < NK; kc++) {
        const int s = kc % NSTAGE;
        mbar_wait(mb0 + 8 * s, (kc / NSTAGE) & 1);
        const __half* A = (const __half*)(sh + s * STAGE_BYTES);
        const __half* B = (const __half*)(sh + s * STAGE_BYTES + TILE_BYTES);
#pragma unroll
        for (int ks = 0; ks < KC / 16; ks++) {
            wmma::fragment<wmma::matrix_a, 16, 16, 16, __half, wmma::row_major> fa[2];
            wmma::fragment<wmma::matrix_b, 16, 16, 16, __half, wmma::col_major> fb[4];
#pragma unroll
            for (int i = 0; i < 2; i++)
                wmma::load_matrix_sync(fa[i], A + (wm * 32 + i * 16) * LDH + ks * 16, LDH);
#pragma unroll
            for (int j = 0; j < 4; j++)
                wmma::load_matrix_sync(fb[j], B + (wn * 64 + j * 16) * LDH + ks * 16, LDH);
#pragma unroll
            for (int i = 0; i < 2; i++)
#pragma unroll
                for (int j = 0; j < 4; j++)
                    wmma::mma_sync(acc[i][j], fa[i], fb[j], acc[i][j]);
        }
        __syncthreads();
        int kn = kc + NSTAGE;
        if (kn < NK && tid == 0) {
            mbar_expect_tx(mb0 + 8 * s, STAGE_BYTES);
            bulk_g2s(sb + s * STAGE_BYTES,              Asrc + (size_t)kn * 128 * LDH, TILE_BYTES, mb0 + 8 * s);
            bulk_g2s(sb + s * STAGE_BYTES + TILE_BYTES, Bsrc + (size_t)kn * 128 * LDH, TILE_BYTES, mb0 + 8 * s);
        }
    }

    // Stage fp32: G frag j<2 -> cols wn*32+j*16 ; U frag j>=2 -> 64+wn*32+(j-2)*16
    float* st = (float*)sh;   // 128 x 132 fp32 = 67584 B <= 110592
    __syncthreads();
#pragma unroll
    for (int i = 0; i < 2; i++)
#pragma unroll
        for (int j = 0; j < 4; j++) {
            int cc = (j < 2) ? (wn * 32 + j * 16) : (64 + wn * 32 + (j - 2) * 16);
            wmma::store_matrix_sync(st + (wm * 32 + i * 16) * LDST + cc,
                                    acc[i][j], LDST, wmma::mem_row_major);
        }
    __syncthreads();

    __half* hdst = g_ht + (size_t)(tile * 32 + y) * 128 * LDH;
#pragma unroll
    for (int j = 0; j < 16; j++) {               // 128 rows x 32 half2 cols
        int p = tid + 256 * j;
        int r = p >> 5, c2 = p & 31;
        float g0 = st[r * LDST + c2 * 2];
        float g1 = st[r * LDST + c2 * 2 + 1];
        float u0 = st[r * LDST + 64 + c2 * 2];
        float u1 = st[r * LDST + 64 + c2 * 2 + 1];
        float h0 = (g0 / (1.0f + __expf(-g0))) * u0;
        float h1 = (g1 / (1.0f + __expf(-g1))) * u1;
        __half2 hv = __floats2half2_rn(h0, h1);
        *(uint32_t*)(hdst + r * LDH + c2 * 2) = *(uint32_t*)&hv;
    }
}

// ---------------------------------------------------------------------------
// GEMM2: Out = H @ Dw^T, 128x128 CTA tile, 8 warps (4x2), warp 32x64.
// A from g_ht tiles, B from g_wdt tiles, one bulk per tile, 3 stages.
// ---------------------------------------------------------------------------
__global__ __launch_bounds__(256, 2) __cluster_dims__(1, 1, 1) void gemm2_kernel(float* __restrict__ out) {
    const int tile = blockIdx.x;
    const int e = g_tile_expert[tile];
    if (e < 0) return;
    const int y = blockIdx.y;
    const int n0 = y * 128;

    extern __shared__ __align__(128) char sh[];
    __shared__ __align__(8) unsigned long long mbars[NSTAGE];
    __shared__ int rowtok[128];
    const uint32_t sb = smem_u32(sh);
    const uint32_t mb0 = smem_u32(mbars);
    const int tid = threadIdx.x;

    if (tid == 0) {
        for (int s = 0; s < NSTAGE; s++) mbar_init(mb0 + 8 * s);
    }
    if (tid < 128) rowtok[tid] = g_perm[tile * TM + tid];
    __syncthreads();

    const __half* Asrc = g_ht  + (size_t)tile * 32 * 128 * LDH;
    const __half* Bsrc = g_wdt + (size_t)((e * 6 + y) * 32) * 128 * LDH;

    const int NK = IDIM / KC;  // 32
    if (tid == 0) {
        FENCE_ASYNC();
#pragma unroll
        for (int s = 0; s < NSTAGE; s++) {
            mbar_expect_tx(mb0 + 8 * s, STAGE_BYTES);
            bulk_g2s(sb + s * STAGE_BYTES,              Asrc + (size_t)s * 128 * LDH, TILE_BYTES, mb0 + 8 * s);
            bulk_g2s(sb + s * STAGE_BYTES + TILE_BYTES, Bsrc + (size_t)s * 128 * LDH, TILE_BYTES, mb0 + 8 * s);
        }
    }

    const int wid = tid >> 5, wm = wid >> 1, wn = wid & 1;
    wmma::fragment<wmma::accumulator, 16, 16, 16, float> acc[2][4];
#pragma unroll
    for (int i = 0; i < 2; i++)
#pragma unroll
        for (int j = 0; j < 4; j++) wmma::fill_fragment(acc[i][j], 0.0f);

    for (int kc = 0; kc < NK; kc++) {
        const int s = kc % NSTAGE;
        mbar_wait(mb0 + 8 * s, (kc / NSTAGE) & 1);
        const __half* A = (const __half*)(sh + s * STAGE_BYTES);
        const __half* B = (const __half*)(sh + s * STAGE_BYTES + TILE_BYTES);
#pragma unroll
        for (int ks = 0; ks < KC / 16; ks++) {
            wmma::fragment<wmma::matrix_a, 16, 16, 16, __half, wmma::row_major> fa[2];
            wmma::fragment<wmma::matrix_b, 16, 16, 16, __half, wmma::col_major> fb[4];
#pragma unroll
            for (int i = 0; i < 2; i++)
                wmma::load_matrix_sync(fa[i], A + (wm * 32 + i * 16) * LDH + ks * 16, LDH);
#pragma unroll
            for (int j = 0; j < 4; j++)
                wmma::load_matrix_sync(fb[j], B + (wn * 64 + j * 16) * LDH + ks * 16, LDH);
#pragma unroll
            for (int i = 0; i < 2; i++)
#pragma unroll
                for (int j = 0; j < 4; j++)
                    wmma::mma_sync(acc[i][j], fa[i], fb[j], acc[i][j]);
        }
        __syncthreads();
        int kn = kc + NSTAGE;
        if (kn < NK && tid == 0) {
            mbar_expect_tx(mb0 + 8 * s, STAGE_BYTES);
            bulk_g2s(sb + s * STAGE_BYTES,              Asrc + (size_t)kn * 128 * LDH, TILE_BYTES, mb0 + 8 * s);
            bulk_g2s(sb + s * STAGE_BYTES + TILE_BYTES, Bsrc + (size_t)kn * 128 * LDH, TILE_BYTES, mb0 + 8 * s);
        }
    }

    // Stage fp32 result (128 x 132), scatter valid rows (float4).
    float* st = (float*)sh;
    __syncthreads();
#pragma unroll
    for (int i = 0; i < 2; i++)
#pragma unroll
        for (int j = 0; j < 4; j++)
            wmma::store_matrix_sync(st + (wm * 32 + i * 16) * LDST + wn * 64 + j * 16,
                                    acc[i][j], LDST, wmma::mem_row_major);
    __syncthreads();
#pragma unroll
    for (int j = 0; j < 16; j++) {               // 128 rows x 32 float4 cols
        int p = tid + 256 * j;
        int r = p >> 5, c4 = (p & 31) * 4;
        int t = rowtok[r];
        if (t >= 0)
            *(float4*)(out + (size_t)t * DDIM + n0 + c4) = *(float4*)&st[r * LDST + c4];
    }
}

// ---------------------------------------------------------------------------
extern "C" void kernel_launch(void* const* d_in, const int* in_sizes, int n_in,
                              void* d_out, int out_size) {
    const float* x   = (const float*)d_in[0];
    const void*  pos = d_in[1];
    // d_in[2] = behavior_index: unused
    const float* gw  = (const float*)d_in[3];
    const float* uw  = (const float*)d_in[4];
    const float* dw  = (const float*)d_in[5];
    float* out = (float*)d_out;

    cudaFuncSetAttribute(gemm1_kernel, cudaFuncAttributeMaxDynamicSharedMemorySize, GSMEM);
    cudaFuncSetAttribute(gemm2_kernel, cudaFuncAttributeMaxDynamicSharedMemorySize, GSMEM);

    route_kernel<<<1, 256>>>(pos);
    cvt_wgu<<<(NEXP * 32 * 12 * 128 * 9 + 255) / 256, 256>>>(gw, uw);
    cvt_wd <<<(NEXP * 6 * 32 * 128 * 9 + 255) / 256, 256>>>(dw);
    cvt_x  <<<(NTILES * 12 * 128 * 9 + 255) / 256, 256>>>(x);
    gemm1_kernel<<<dim3(NTILES, IDIM / 64), 256, GSMEM>>>();
    gemm2_kernel<<<dim3(NTILES, DDIM / 128), 256, GSMEM>>>(out);
}

// round 8
// speedup vs baseline: 1.2574x; 1.0401x over previous
#include <cuda_runtime.h>
#include <cuda_fp16.h>
#include <mma.h>
#include <cstdint>

using namespace nvcuda;

#define T_TOK 4096
#define DDIM  768
#define IDIM  2048
#define NEXP  8
#define TM    128
#define NTILES 40
#define PADROWS (NTILES*TM)
#define KC    64             // halves per K chunk
#define LDH   72             // padded row length (halves): 144B rows, conflict-free ldmatrix
#define LDST  132            // fp32 staging stride (gemm2): %4==0, row %16B==0
#define LDST2 68             // fp32 staging stride (gemm1, 64 cols)
#define TILE_BYTES (128 * LDH * 2)       // 18432 B contiguous A or B chunk
#define STAGE_BYTES (2 * TILE_BYTES)     // 36864
#define NSTAGE 2
#define GSMEM (NSTAGE * STAGE_BYTES)     // 73728 -> 3 CTA/SM

// ---------------- device-global scratch (tiled layouts, no allocation) ------
__device__ int    g_perm[PADROWS];
__device__ int    g_tile_expert[NTILES];
// [e][y:32][kc:12][r:128][72]  rows interleaved [G0-31|U0-31|G32-63|U32-63]
__device__ __half g_wgu[(size_t)NEXP * 32 * 12 * 128 * LDH];
// [e][y:6][kc:32][r:128][72]
__device__ __half g_wdt[(size_t)NEXP * 6 * 32 * 128 * LDH];
// [tile:40][kc:12][r:128][72]  rows already permuted (pad rows = 0)
__device__ __half g_xt [(size_t)NTILES * 12 * 128 * LDH];
// [tile:40][kc:32][r:128][72]
__device__ __half g_ht [(size_t)NTILES * 32 * 128 * LDH];
// split-K partials, permuted row order: [z:2][PADROWS][768]
__device__ float  g_gp [(size_t)2 * PADROWS * DDIM];

// ---------------- PTX helpers -----------------------------------------------
__device__ __forceinline__ uint32_t smem_u32(const void* p) {
    uint32_t a;
    asm("{ .reg .u64 t; cvta.to.shared.u64 t, %1; cvt.u32.u64 %0, t; }" : "=r"(a) : "l"(p));
    return a;
}
__device__ __forceinline__ void mbar_init(uint32_t a) {
    asm volatile("mbarrier.init.shared.b64 [%0], 1;" :: "r"(a) : "memory");
}
__device__ __forceinline__ void mbar_expect_tx(uint32_t a, uint32_t bytes) {
    asm volatile("mbarrier.arrive.expect_tx.shared.b64 _, [%0], %1;" :: "r"(a), "r"(bytes) : "memory");
}
__device__ __forceinline__ void mbar_wait(uint32_t mbar, int parity) {
    asm volatile(
        "{\n\t.reg .pred P;\n\t"
        "WL_%=:\n\t"
        "mbarrier.try_wait.parity.acquire.cta.shared::cta.b64 P, [%0], %1, 0x989680;\n\t"
        "@P bra.uni WD_%=;\n\t"
        "bra.uni WL_%=;\n\t"
        "WD_%=:\n\t}"
        :: "r"(mbar), "r"(parity) : "memory");
}
__device__ __forceinline__ void bulk_g2s(uint32_t dst, const void* src, uint32_t bytes, uint32_t mbar) {
    asm volatile(
        "cp.async.bulk.shared::cluster.global.mbarrier::complete_tx::bytes [%0], [%1], %2, [%3];"
        :: "r"(dst), "l"(src), "r"(bytes), "r"(mbar) : "memory");
}
#define FENCE_ASYNC() asm volatile("fence.proxy.async.shared::cta;" ::: "memory")

// ---------------------------------------------------------------------------
// Routing (int64/int32 safe)
// ---------------------------------------------------------------------------
__global__ void route_kernel(const void* __restrict__ pos) {
    __shared__ int cnt[NEXP], off[NEXP], cur[NEXP];
    __shared__ int s_not64;
    const int tid = threadIdx.x;
    if (tid < NEXP) { cnt[tid] = 0; cur[tid] = 0; }
    if (tid == 0) s_not64 = 0;
    __syncthreads();
    const unsigned long long* pl = (const unsigned long long*)pos;
    for (int i = tid; i < T_TOK / 2; i += blockDim.x)
        if (pl[i] > 7ULL) s_not64 = 1;
    __syncthreads();
    const int is64 = !s_not64;
    const long long* p64 = (const long long*)pos;
    const int*       p32 = (const int*)pos;
    for (int t = tid; t < T_TOK; t += blockDim.x) {
        int e = is64 ? (int)p64[t] : p32[t];
        atomicAdd(&cnt[e], 1);
    }
    for (int i = tid; i < PADROWS; i += blockDim.x) g_perm[i] = -1;
    __syncthreads();
    if (tid == 0) {
        int o = 0;
        for (int e = 0; e < NEXP; e++) {
            off[e] = o;
            int nt = (cnt[e] + TM - 1) / TM;
            for (int k = 0; k < nt; k++) g_tile_expert[o / TM + k] = e;
            o += nt * TM;
        }
        for (int tl = o / TM; tl < NTILES; tl++) g_tile_expert[tl] = -1;
    }
    __syncthreads();
    for (int t = tid; t < T_TOK; t += blockDim.x) {
        int e = is64 ? (int)p64[t] : p32[t];
        int p = off[e] + atomicAdd(&cur[e], 1);
        g_perm[p] = t;
    }
}

// ---------------------------------------------------------------------------
// cvt: fp32 -> fp16 into tiled layouts (dst offset == idx*8 halves by design)
// ---------------------------------------------------------------------------
__device__ __forceinline__ uint4 cvt8(const float* src) {
    float4 v0 = *(const float4*)src;
    float4 v1 = *(const float4*)(src + 4);
    __half2 h0 = __floats2half2_rn(v0.x, v0.y), h1 = __floats2half2_rn(v0.z, v0.w);
    __half2 h2 = __floats2half2_rn(v1.x, v1.y), h3 = __floats2half2_rn(v1.z, v1.w);
    uint4 o;
    o.x = *(uint32_t*)&h0; o.y = *(uint32_t*)&h1;
    o.z = *(uint32_t*)&h2; o.w = *(uint32_t*)&h3;
    return o;
}

__global__ void cvt_wgu(const float* __restrict__ gw, const float* __restrict__ uw) {
    const int TOT = NEXP * 32 * 12 * 128 * 9;
    int idx = blockIdx.x * 256 + threadIdx.x;
    if (idx >= TOT) return;
    int c8 = idx % 9; int t1 = idx / 9;
    int r  = t1 % 128; t1 /= 128;
    int kc = t1 % 12;  t1 /= 12;
    int y  = t1 % 32;  int e = t1 / 32;
    uint4 o = make_uint4(0, 0, 0, 0);
    if (c8 < 8) {
        int q = r & 63;
        int wrow = y * 64 + (r >> 6) * 32 + (q & 31);
        const float* src = ((q < 32) ? gw : uw) + ((size_t)e * IDIM + wrow) * DDIM + kc * 64 + c8 * 8;
        o = cvt8(src);
    }
    *(uint4*)(g_wgu + (size_t)idx * 8) = o;
}

__global__ void cvt_wd(const float* __restrict__ dw) {
    const int TOT = NEXP * 6 * 32 * 128 * 9;
    int idx = blockIdx.x * 256 + threadIdx.x;
    if (idx >= TOT) return;
    int c8 = idx % 9; int t1 = idx / 9;
    int r  = t1 % 128; t1 /= 128;
    int kc = t1 % 32;  t1 /= 32;
    int y  = t1 % 6;   int e = t1 / 6;
    uint4 o = make_uint4(0, 0, 0, 0);
    if (c8 < 8) {
        const float* src = dw + ((size_t)e * DDIM + y * 128 + r) * IDIM + kc * 64 + c8 * 8;
        o = cvt8(src);
    }
    *(uint4*)(g_wdt + (size_t)idx * 8) = o;
}

__global__ void cvt_x(const float* __restrict__ x) {   // run AFTER route
    const int TOT = NTILES * 12 * 128 * 9;
    int idx = blockIdx.x * 256 + threadIdx.x;
    if (idx >= TOT) return;
    int c8 = idx % 9; int t1 = idx / 9;
    int r  = t1 % 128; t1 /= 128;
    int kc = t1 % 12;  int tile = t1 / 12;
    uint4 o = make_uint4(0, 0, 0, 0);
    int t = g_perm[tile * TM + r];
    if (c8 < 8 && t >= 0)
        o = cvt8(x + (size_t)t * DDIM + kc * 64 + c8 * 8);
    *(uint4*)(g_xt + (size_t)idx * 8) = o;
}

// ---------------------------------------------------------------------------
// GEMM1: 128x128 CTA tile (64 G cols + 64 U cols), 4 warps (2x2), warp 64x64.
// acc[i][j<2] = G cols wn*32+j*16, acc[i][j>=2] = U same cols -> in-register
// silu(G)*U (identical elementwise fragment layouts). 2-stage bulk pipeline.
// ---------------------------------------------------------------------------
__global__ __launch_bounds__(128, 3) __cluster_dims__(1, 1, 1) void gemm1_kernel() {
    const int tile = blockIdx.x;
    const int e = g_tile_expert[tile];
    if (e < 0) return;
    const int y = blockIdx.y;          // 64-col block (== gemm2 k-chunk index)

    extern __shared__ __align__(128) char sh[];
    __shared__ __align__(8) unsigned long long mbars[NSTAGE];
    const uint32_t sb = smem_u32(sh);
    const uint32_t mb0 = smem_u32(mbars);
    const int tid = threadIdx.x;

    if (tid == 0)
        for (int s = 0; s < NSTAGE; s++) mbar_init(mb0 + 8 * s);
    __syncthreads();

    const __half* Asrc = g_xt  + (size_t)tile * 12 * 128 * LDH;
    const __half* Bsrc = g_wgu + (size_t)((e * 32 + y) * 12) * 128 * LDH;

    const int NK = DDIM / KC;  // 12
    if (tid == 0) {
        FENCE_ASYNC();
#pragma unroll
        for (int s = 0; s < NSTAGE; s++) {
            mbar_expect_tx(mb0 + 8 * s, STAGE_BYTES);
            bulk_g2s(sb + s * STAGE_BYTES,              Asrc + (size_t)s * 128 * LDH, TILE_BYTES, mb0 + 8 * s);
            bulk_g2s(sb + s * STAGE_BYTES + TILE_BYTES, Bsrc + (size_t)s * 128 * LDH, TILE_BYTES, mb0 + 8 * s);
        }
    }

    const int wid = tid >> 5, wm = wid >> 1, wn = wid & 1;
    wmma::fragment<wmma::accumulator, 16, 16, 16, float> acc[4][4];
#pragma unroll
    for (int i = 0; i < 4; i++)
#pragma unroll
        for (int j = 0; j < 4; j++) wmma::fill_fragment(acc[i][j], 0.0f);

    for (int kc = 0; kc < NK; kc++) {
        const int s = kc & 1;
        mbar_wait(mb0 + 8 * s, (kc >> 1) & 1);
        const __half* A = (const __half*)(sh + s * STAGE_BYTES);
        const __half* B = (const __half*)(sh + s * STAGE_BYTES + TILE_BYTES);
#pragma unroll
        for (int ks = 0; ks < KC / 16; ks++) {
            wmma::fragment<wmma::matrix_a, 16, 16, 16, __half, wmma::row_major> fa[4];
            wmma::fragment<wmma::matrix_b, 16, 16, 16, __half, wmma::col_major> fb[4];
#pragma unroll
            for (int i = 0; i < 4; i++)
                wmma::load_matrix_sync(fa[i], A + (wm * 64 + i * 16) * LDH + ks * 16, LDH);
#pragma unroll
            for (int j = 0; j < 4; j++)
                wmma::load_matrix_sync(fb[j], B + (wn * 64 + j * 16) * LDH + ks * 16, LDH);
#pragma unroll
            for (int i = 0; i < 4; i++)
#pragma unroll
                for (int j = 0; j < 4; j++)
                    wmma::mma_sync(acc[i][j], fa[i], fb[j], acc[i][j]);
        }
        __syncthreads();
        int kn = kc + NSTAGE;
        if (kn < NK && tid == 0) {
            mbar_expect_tx(mb0 + 8 * s, STAGE_BYTES);
            bulk_g2s(sb + s * STAGE_BYTES,              Asrc + (size_t)kn * 128 * LDH, TILE_BYTES, mb0 + 8 * s);
            bulk_g2s(sb + s * STAGE_BYTES + TILE_BYTES, Bsrc + (size_t)kn * 128 * LDH, TILE_BYTES, mb0 + 8 * s);
        }
    }

    // In-register silu(G)*U, stage fp32 h (128 x 64, stride 68), write fp16 tile
    float* st = (float*)sh;   // 128*68*4 = 34816 B <= 73728
    __syncthreads();
#pragma unroll
    for (int i = 0; i < 4; i++)
#pragma unroll
        for (int jj = 0; jj < 2; jj++) {
#pragma unroll
            for (int el = 0; el < acc[i][jj].num_elements; el++) {
                float g = acc[i][jj].x[el];
                float u = acc[i][jj + 2].x[el];
                acc[i][jj].x[el] = (g / (1.0f + __expf(-g))) * u;
            }
            wmma::store_matrix_sync(st + (wm * 64 + i * 16) * LDST2 + wn * 32 + jj * 16,
                                    acc[i][jj], LDST2, wmma::mem_row_major);
        }
    __syncthreads();

    __half* hdst = g_ht + (size_t)(tile * 32 + y) * 128 * LDH;
#pragma unroll
    for (int j = 0; j < 32; j++) {               // 128 rows x 32 half2 cols
        int p = tid + 128 * j;
        int r = p >> 5, c2 = p & 31;
        float h0 = st[r * LDST2 + c2 * 2];
        float h1 = st[r * LDST2 + c2 * 2 + 1];
        __half2 hv = __floats2half2_rn(h0, h1);
        *(uint32_t*)(hdst + r * LDH + c2 * 2) = *(uint32_t*)&hv;
    }
}

// ---------------------------------------------------------------------------
// GEMM2: split-K (z=0: kc 0-15, z=1: kc 16-31). 128x128 CTA, 4 warps, 64x64.
// Writes permuted-order fp32 partials g_gp[z]; add_kernel combines + scatters.
// ---------------------------------------------------------------------------
__global__ __launch_bounds__(128, 3) __cluster_dims__(1, 1, 1) void gemm2_kernel() {
    const int tile = blockIdx.x;
    const int e = g_tile_expert[tile];
    if (e < 0) return;
    const int y = blockIdx.y;
    const int z = blockIdx.z;

    extern __shared__ __align__(128) char sh[];
    __shared__ __align__(8) unsigned long long mbars[NSTAGE];
    const uint32_t sb = smem_u32(sh);
    const uint32_t mb0 = smem_u32(mbars);
    const int tid = threadIdx.x;

    if (tid == 0)
        for (int s = 0; s < NSTAGE; s++) mbar_init(mb0 + 8 * s);
    __syncthreads();

    const __half* Asrc = g_ht  + (size_t)(tile * 32 + z * 16) * 128 * LDH;
    const __half* Bsrc = g_wdt + (size_t)((e * 6 + y) * 32 + z * 16) * 128 * LDH;

    const int NK = 16;
    if (tid == 0) {
        FENCE_ASYNC();
#pragma unroll
        for (int s = 0; s < NSTAGE; s++) {
            mbar_expect_tx(mb0 + 8 * s, STAGE_BYTES);
            bulk_g2s(sb + s * STAGE_BYTES,              Asrc + (size_t)s * 128 * LDH, TILE_BYTES, mb0 + 8 * s);
            bulk_g2s(sb + s * STAGE_BYTES + TILE_BYTES, Bsrc + (size_t)s * 128 * LDH, TILE_BYTES, mb0 + 8 * s);
        }
    }

    const int wid = tid >> 5, wm = wid >> 1, wn = wid & 1;
    wmma::fragment<wmma::accumulator, 16, 16, 16, float> acc[4][4];
#pragma unroll
    for (int i = 0; i < 4; i++)
#pragma unroll
        for (int j = 0; j < 4; j++) wmma::fill_fragment(acc[i][j], 0.0f);

    for (int kc = 0; kc < NK; kc++) {
        const int s = kc & 1;
        mbar_wait(mb0 + 8 * s, (kc >> 1) & 1);
        const __half* A = (const __half*)(sh + s * STAGE_BYTES);
        const __half* B = (const __half*)(sh + s * STAGE_BYTES + TILE_BYTES);
#pragma unroll
        for (int ks = 0; ks < KC / 16; ks++) {
            wmma::fragment<wmma::matrix_a, 16, 16, 16, __half, wmma::row_major> fa[4];
            wmma::fragment<wmma::matrix_b, 16, 16, 16, __half, wmma::col_major> fb[4];
#pragma unroll
            for (int i = 0; i < 4; i++)
                wmma::load_matrix_sync(fa[i], A + (wm * 64 + i * 16) * LDH + ks * 16, LDH);
#pragma unroll
            for (int j = 0; j < 4; j++)
                wmma::load_matrix_sync(fb[j], B + (wn * 64 + j * 16) * LDH + ks * 16, LDH);
#pragma unroll
            for (int i = 0; i < 4; i++)
#pragma unroll
                for (int j = 0; j < 4; j++)
                    wmma::mma_sync(acc[i][j], fa[i], fb[j], acc[i][j]);
        }
        __syncthreads();
        int kn = kc + NSTAGE;
        if (kn < NK && tid == 0) {
            mbar_expect_tx(mb0 + 8 * s, STAGE_BYTES);
            bulk_g2s(sb + s * STAGE_BYTES,              Asrc + (size_t)kn * 128 * LDH, TILE_BYTES, mb0 + 8 * s);
            bulk_g2s(sb + s * STAGE_BYTES + TILE_BYTES, Bsrc + (size_t)kn * 128 * LDH, TILE_BYTES, mb0 + 8 * s);
        }
    }

    // Stage fp32 (128 x 132), write partial (permuted order, no scatter).
    float* st = (float*)sh;
    __syncthreads();
#pragma unroll
    for (int i = 0; i < 4; i++)
#pragma unroll
        for (int j = 0; j < 4; j++)
            wmma::store_matrix_sync(st + (wm * 64 + i * 16) * LDST + wn * 64 + j * 16,
                                    acc[i][j], LDST, wmma::mem_row_major);
    __syncthreads();

    float* dst = g_gp + ((size_t)z * PADROWS + tile * 128) * DDIM + y * 128;
#pragma unroll
    for (int j = 0; j < 32; j++) {               // 128 rows x 32 float4 cols
        int p = tid + 128 * j;
        int r = p >> 5, c4 = (p & 31) * 4;
        *(float4*)(dst + (size_t)r * DDIM + c4) = *(float4*)&st[r * LDST + c4];
    }
}

// ---------------------------------------------------------------------------
// add partials + scatter to output
// ---------------------------------------------------------------------------
__global__ void add_kernel(float* __restrict__ out) {
    int idx = blockIdx.x * 256 + threadIdx.x;    // over PADROWS * 192 float4
    if (idx >= PADROWS * (DDIM / 4)) return;
    int p = idx / (DDIM / 4), c4 = (idx % (DDIM / 4)) * 4;
    int t = g_perm[p];
    if (t < 0) return;
    const float* a = g_gp + (size_t)p * DDIM + c4;
    const float* b = g_gp + (size_t)(PADROWS + p) * DDIM + c4;
    float4 va = *(const float4*)a, vb = *(const float4*)b;
    float4 o = make_float4(va.x + vb.x, va.y + vb.y, va.z + vb.z, va.w + vb.w);
    *(float4*)(out + (size_t)t * DDIM + c4) = o;
}

// ---------------------------------------------------------------------------
extern "C" void kernel_launch(void* const* d_in, const int* in_sizes, int n_in,
                              void* d_out, int out_size) {
    const float* x   = (const float*)d_in[0];
    const void*  pos = d_in[1];
    // d_in[2] = behavior_index: unused
    const float* gw  = (const float*)d_in[3];
    const float* uw  = (const float*)d_in[4];
    const float* dw  = (const float*)d_in[5];
    float* out = (float*)d_out;

    cudaFuncSetAttribute(gemm1_kernel, cudaFuncAttributeMaxDynamicSharedMemorySize, GSMEM);
    cudaFuncSetAttribute(gemm2_kernel, cudaFuncAttributeMaxDynamicSharedMemorySize, GSMEM);

    route_kernel<<<1, 256>>>(pos);
    cvt_x  <<<(NTILES * 12 * 128 * 9 + 255) / 256, 256>>>(x);
    cvt_wgu<<<(NEXP * 32 * 12 * 128 * 9 + 255) / 256, 256>>>(gw, uw);
    cvt_wd <<<(NEXP * 6 * 32 * 128 * 9 + 255) / 256, 256>>>(dw);
    gemm1_kernel<<<dim3(NTILES, 32), 128, GSMEM>>>();
    gemm2_kernel<<<dim3(NTILES, 6, 2), 128, GSMEM>>>();
    add_kernel<<<(PADROWS * (DDIM / 4) + 255) / 256, 256>>>(out);
}

// round 9
// speedup vs baseline: 1.3153x; 1.0461x over previous
#include <cuda_runtime.h>
#include <cuda_fp16.h>
#include <mma.h>
#include <cstdint>

using namespace nvcuda;

#define T_TOK 4096
#define DDIM  768
#define IDIM  2048
#define NEXP  8
#define TM    128
#define NTILES 40
#define PADROWS (NTILES*TM)
#define KC    64             // halves per K chunk
#define LDH   72             // padded row length (halves): 144B rows, conflict-free ldmatrix
#define LDST  132            // fp32 staging stride (gemm2): %4==0, row %16B==0
#define LDST2 68             // fp32 staging stride (gemm1, 64 cols)
#define TILE_BYTES (128 * LDH * 2)       // 18432 B contiguous A or B chunk
#define STAGE_BYTES (2 * TILE_BYTES)     // 36864
#define NSTAGE 2
#define GSMEM (NSTAGE * STAGE_BYTES)     // 73728 -> 3 CTA/SM

// ---------------- device-global scratch (tiled layouts, no allocation) ------
__device__ int    g_perm[PADROWS];
__device__ int    g_tile_expert[NTILES];
// [e][y:32][kc:12][r:128][72]  rows interleaved [G0-31|U0-31|G32-63|U32-63]
__device__ __half g_wgu[(size_t)NEXP * 32 * 12 * 128 * LDH];
// [e][y:6][kc:32][r:128][72]
__device__ __half g_wdt[(size_t)NEXP * 6 * 32 * 128 * LDH];
// [tile:40][kc:12][r:128][72]  rows already permuted (pad rows = 0)
__device__ __half g_xt [(size_t)NTILES * 12 * 128 * LDH];
// [tile:40][kc:32][r:128][72]
__device__ __half g_ht [(size_t)NTILES * 32 * 128 * LDH];
// split-K partials, permuted row order: [z:2][PADROWS][768]
__device__ float  g_gp [(size_t)2 * PADROWS * DDIM];

// ---------------- PTX helpers -----------------------------------------------
__device__ __forceinline__ uint32_t smem_u32(const void* p) {
    uint32_t a;
    asm("{ .reg .u64 t; cvta.to.shared.u64 t, %1; cvt.u32.u64 %0, t; }" : "=r"(a) : "l"(p));
    return a;
}
__device__ __forceinline__ void mbar_init(uint32_t a) {
    asm volatile("mbarrier.init.shared.b64 [%0], 1;" :: "r"(a) : "memory");
}
__device__ __forceinline__ void mbar_expect_tx(uint32_t a, uint32_t bytes) {
    asm volatile("mbarrier.arrive.expect_tx.shared.b64 _, [%0], %1;" :: "r"(a), "r"(bytes) : "memory");
}
__device__ __forceinline__ void mbar_wait(uint32_t mbar, int parity) {
    asm volatile(
        "{\n\t.reg .pred P;\n\t"
        "WL_%=:\n\t"
        "mbarrier.try_wait.parity.acquire.cta.shared::cta.b64 P, [%0], %1, 0x989680;\n\t"
        "@P bra.uni WD_%=;\n\t"
        "bra.uni WL_%=;\n\t"
        "WD_%=:\n\t}"
        :: "r"(mbar), "r"(parity) : "memory");
}
__device__ __forceinline__ void bulk_g2s(uint32_t dst, const void* src, uint32_t bytes, uint32_t mbar) {
    asm volatile(
        "cp.async.bulk.shared::cluster.global.mbarrier::complete_tx::bytes [%0], [%1], %2, [%3];"
        :: "r"(dst), "l"(src), "r"(bytes), "r"(mbar) : "memory");
}
#define FENCE_ASYNC() asm volatile("fence.proxy.async.shared::cta;" ::: "memory")

// ---------------------------------------------------------------------------
// Routing (int64/int32 safe)
// ---------------------------------------------------------------------------
__global__ void route_kernel(const void* __restrict__ pos) {
    __shared__ int cnt[NEXP], off[NEXP], cur[NEXP];
    __shared__ int s_not64;
    const int tid = threadIdx.x;
    if (tid < NEXP) { cnt[tid] = 0; cur[tid] = 0; }
    if (tid == 0) s_not64 = 0;
    __syncthreads();
    const unsigned long long* pl = (const unsigned long long*)pos;
    for (int i = tid; i < T_TOK / 2; i += blockDim.x)
        if (pl[i] > 7ULL) s_not64 = 1;
    __syncthreads();
    const int is64 = !s_not64;
    const long long* p64 = (const long long*)pos;
    const int*       p32 = (const int*)pos;
    for (int t = tid; t < T_TOK; t += blockDim.x) {
        int e = is64 ? (int)p64[t] : p32[t];
        atomicAdd(&cnt[e], 1);
    }
    for (int i = tid; i < PADROWS; i += blockDim.x) g_perm[i] = -1;
    __syncthreads();
    if (tid == 0) {
        int o = 0;
        for (int e = 0; e < NEXP; e++) {
            off[e] = o;
            int nt = (cnt[e] + TM - 1) / TM;
            for (int k = 0; k < nt; k++) g_tile_expert[o / TM + k] = e;
            o += nt * TM;
        }
        for (int tl = o / TM; tl < NTILES; tl++) g_tile_expert[tl] = -1;
    }
    __syncthreads();
    for (int t = tid; t < T_TOK; t += blockDim.x) {
        int e = is64 ? (int)p64[t] : p32[t];
        int p = off[e] + atomicAdd(&cur[e], 1);
        g_perm[p] = t;
    }
}

// ---------------------------------------------------------------------------
// cvt: fp32 -> fp16 into tiled layouts (dst offset == idx*8 halves by design)
// ---------------------------------------------------------------------------
__device__ __forceinline__ uint4 cvt8(const float* src) {
    float4 v0 = *(const float4*)src;
    float4 v1 = *(const float4*)(src + 4);
    __half2 h0 = __floats2half2_rn(v0.x, v0.y), h1 = __floats2half2_rn(v0.z, v0.w);
    __half2 h2 = __floats2half2_rn(v1.x, v1.y), h3 = __floats2half2_rn(v1.z, v1.w);
    uint4 o;
    o.x = *(uint32_t*)&h0; o.y = *(uint32_t*)&h1;
    o.z = *(uint32_t*)&h2; o.w = *(uint32_t*)&h3;
    return o;
}

__global__ void cvt_wgu(const float* __restrict__ gw, const float* __restrict__ uw) {
    const int TOT = NEXP * 32 * 12 * 128 * 9;
    int idx = blockIdx.x * 256 + threadIdx.x;
    if (idx >= TOT) return;
    int c8 = idx % 9; int t1 = idx / 9;
    int r  = t1 % 128; t1 /= 128;
    int kc = t1 % 12;  t1 /= 12;
    int y  = t1 % 32;  int e = t1 / 32;
    uint4 o = make_uint4(0, 0, 0, 0);
    if (c8 < 8) {
        int q = r & 63;
        int wrow = y * 64 + (r >> 6) * 32 + (q & 31);
        const float* src = ((q < 32) ? gw : uw) + ((size_t)e * IDIM + wrow) * DDIM + kc * 64 + c8 * 8;
        o = cvt8(src);
    }
    *(uint4*)(g_wgu + (size_t)idx * 8) = o;
}

__global__ void cvt_wd(const float* __restrict__ dw) {
    const int TOT = NEXP * 6 * 32 * 128 * 9;
    int idx = blockIdx.x * 256 + threadIdx.x;
    if (idx >= TOT) return;
    int c8 = idx % 9; int t1 = idx / 9;
    int r  = t1 % 128; t1 /= 128;
    int kc = t1 % 32;  t1 /= 32;
    int y  = t1 % 6;   int e = t1 / 6;
    uint4 o = make_uint4(0, 0, 0, 0);
    if (c8 < 8) {
        const float* src = dw + ((size_t)e * DDIM + y * 128 + r) * IDIM + kc * 64 + c8 * 8;
        o = cvt8(src);
    }
    *(uint4*)(g_wdt + (size_t)idx * 8) = o;
}

__global__ void cvt_x(const float* __restrict__ x) {   // run AFTER route
    const int TOT = NTILES * 12 * 128 * 9;
    int idx = blockIdx.x * 256 + threadIdx.x;
    if (idx >= TOT) return;
    int c8 = idx % 9; int t1 = idx / 9;
    int r  = t1 % 128; t1 /= 128;
    int kc = t1 % 12;  int tile = t1 / 12;
    uint4 o = make_uint4(0, 0, 0, 0);
    int t = g_perm[tile * TM + r];
    if (c8 < 8 && t >= 0)
        o = cvt8(x + (size_t)t * DDIM + kc * 64 + c8 * 8);
    *(uint4*)(g_xt + (size_t)idx * 8) = o;
}

// ---------------------------------------------------------------------------
// GEMM1: 128x128 CTA tile (64 G cols + 64 U cols), 4 warps (2x2), warp 64x64.
// In-register silu(G)*U. 2-stage bulk-copy pipeline, 3 CTA/SM.
// ---------------------------------------------------------------------------
__global__ __launch_bounds__(128, 3) __cluster_dims__(1, 1, 1) void gemm1_kernel() {
    const int tile = blockIdx.x;
    const int e = g_tile_expert[tile];
    if (e < 0) return;
    const int y = blockIdx.y;          // 64-col block (== gemm2 k-chunk index)

    extern __shared__ __align__(128) char sh[];
    __shared__ __align__(8) unsigned long long mbars[NSTAGE];
    const uint32_t sb = smem_u32(sh);
    const uint32_t mb0 = smem_u32(mbars);
    const int tid = threadIdx.x;

    if (tid == 0)
        for (int s = 0; s < NSTAGE; s++) mbar_init(mb0 + 8 * s);
    __syncthreads();

    const __half* Asrc = g_xt  + (size_t)tile * 12 * 128 * LDH;
    const __half* Bsrc = g_wgu + (size_t)((e * 32 + y) * 12) * 128 * LDH;

    const int NK = DDIM / KC;  // 12
    if (tid == 0) {
        FENCE_ASYNC();
#pragma unroll
        for (int s = 0; s < NSTAGE; s++) {
            mbar_expect_tx(mb0 + 8 * s, STAGE_BYTES);
            bulk_g2s(sb + s * STAGE_BYTES,              Asrc + (size_t)s * 128 * LDH, TILE_BYTES, mb0 + 8 * s);
            bulk_g2s(sb + s * STAGE_BYTES + TILE_BYTES, Bsrc + (size_t)s * 128 * LDH, TILE_BYTES, mb0 + 8 * s);
        }
    }

    const int wid = tid >> 5, wm = wid >> 1, wn = wid & 1;
    wmma::fragment<wmma::accumulator, 16, 16, 16, float> acc[4][4];
#pragma unroll
    for (int i = 0; i < 4; i++)
#pragma unroll
        for (int j = 0; j < 4; j++) wmma::fill_fragment(acc[i][j], 0.0f);

    for (int kc = 0; kc < NK; kc++) {
        const int s = kc & 1;
        mbar_wait(mb0 + 8 * s, (kc >> 1) & 1);
        const __half* A = (const __half*)(sh + s * STAGE_BYTES);
        const __half* B = (const __half*)(sh + s * STAGE_BYTES + TILE_BYTES);
#pragma unroll
        for (int ks = 0; ks < KC / 16; ks++) {
            wmma::fragment<wmma::matrix_a, 16, 16, 16, __half, wmma::row_major> fa[4];
            wmma::fragment<wmma::matrix_b, 16, 16, 16, __half, wmma::col_major> fb[4];
#pragma unroll
            for (int i = 0; i < 4; i++)
                wmma::load_matrix_sync(fa[i], A + (wm * 64 + i * 16) * LDH + ks * 16, LDH);
#pragma unroll
            for (int j = 0; j < 4; j++)
                wmma::load_matrix_sync(fb[j], B + (wn * 64 + j * 16) * LDH + ks * 16, LDH);
#pragma unroll
            for (int i = 0; i < 4; i++)
#pragma unroll
                for (int j = 0; j < 4; j++)
                    wmma::mma_sync(acc[i][j], fa[i], fb[j], acc[i][j]);
        }
        __syncthreads();
        int kn = kc + NSTAGE;
        if (kn < NK && tid == 0) {
            mbar_expect_tx(mb0 + 8 * s, STAGE_BYTES);
            bulk_g2s(sb + s * STAGE_BYTES,              Asrc + (size_t)kn * 128 * LDH, TILE_BYTES, mb0 + 8 * s);
            bulk_g2s(sb + s * STAGE_BYTES + TILE_BYTES, Bsrc + (size_t)kn * 128 * LDH, TILE_BYTES, mb0 + 8 * s);
        }
    }

    // In-register silu(G)*U, stage fp32 h (128 x 64, stride 68), write fp16 tile
    float* st = (float*)sh;   // 128*68*4 = 34816 B <= 73728
    __syncthreads();
#pragma unroll
    for (int i = 0; i < 4; i++)
#pragma unroll
        for (int jj = 0; jj < 2; jj++) {
#pragma unroll
            for (int el = 0; el < acc[i][jj].num_elements; el++) {
                float g = acc[i][jj].x[el];
                float u = acc[i][jj + 2].x[el];
                acc[i][jj].x[el] = (g / (1.0f + __expf(-g))) * u;
            }
            wmma::store_matrix_sync(st + (wm * 64 + i * 16) * LDST2 + wn * 32 + jj * 16,
                                    acc[i][jj], LDST2, wmma::mem_row_major);
        }
    __syncthreads();

    __half* hdst = g_ht + (size_t)(tile * 32 + y) * 128 * LDH;
#pragma unroll
    for (int j = 0; j < 32; j++) {               // 128 rows x 32 half2 cols
        int p = tid + 128 * j;
        int r = p >> 5, c2 = p & 31;
        float h0 = st[r * LDST2 + c2 * 2];
        float h1 = st[r * LDST2 + c2 * 2 + 1];
        __half2 hv = __floats2half2_rn(h0, h1);
        *(uint32_t*)(hdst + r * LDH + c2 * 2) = *(uint32_t*)&hv;
    }
}

// ---------------------------------------------------------------------------
// GEMM2: split-K (z=0: kc 0-15, z=1: kc 16-31). 128x128 CTA, 4 warps, 64x64.
// ---------------------------------------------------------------------------
__global__ __launch_bounds__(128, 3) __cluster_dims__(1, 1, 1) void gemm2_kernel() {
    const int tile = blockIdx.x;
    const int e = g_tile_expert[tile];
    if (e < 0) return;
    const int y = blockIdx.y;
    const int z = blockIdx.z;

    extern __shared__ __align__(128) char sh[];
    __shared__ __align__(8) unsigned long long mbars[NSTAGE];
    const uint32_t sb = smem_u32(sh);
    const uint32_t mb0 = smem_u32(mbars);
    const int tid = threadIdx.x;

    if (tid == 0)
        for (int s = 0; s < NSTAGE; s++) mbar_init(mb0 + 8 * s);
    __syncthreads();

    const __half* Asrc = g_ht  + (size_t)(tile * 32 + z * 16) * 128 * LDH;
    const __half* Bsrc = g_wdt + (size_t)((e * 6 + y) * 32 + z * 16) * 128 * LDH;

    const int NK = 16;
    if (tid == 0) {
        FENCE_ASYNC();
#pragma unroll
        for (int s = 0; s < NSTAGE; s++) {
            mbar_expect_tx(mb0 + 8 * s, STAGE_BYTES);
            bulk_g2s(sb + s * STAGE_BYTES,              Asrc + (size_t)s * 128 * LDH, TILE_BYTES, mb0 + 8 * s);
            bulk_g2s(sb + s * STAGE_BYTES + TILE_BYTES, Bsrc + (size_t)s * 128 * LDH, TILE_BYTES, mb0 + 8 * s);
        }
    }

    const int wid = tid >> 5, wm = wid >> 1, wn = wid & 1;
    wmma::fragment<wmma::accumulator, 16, 16, 16, float> acc[4][4];
#pragma unroll
    for (int i = 0; i < 4; i++)
#pragma unroll
        for (int j = 0; j < 4; j++) wmma::fill_fragment(acc[i][j], 0.0f);

    for (int kc = 0; kc < NK; kc++) {
        const int s = kc & 1;
        mbar_wait(mb0 + 8 * s, (kc >> 1) & 1);
        const __half* A = (const __half*)(sh + s * STAGE_BYTES);
        const __half* B = (const __half*)(sh + s * STAGE_BYTES + TILE_BYTES);
#pragma unroll
        for (int ks = 0; ks < KC / 16; ks++) {
            wmma::fragment<wmma::matrix_a, 16, 16, 16, __half, wmma::row_major> fa[4];
            wmma::fragment<wmma::matrix_b, 16, 16, 16, __half, wmma::col_major> fb[4];
#pragma unroll
            for (int i = 0; i < 4; i++)
                wmma::load_matrix_sync(fa[i], A + (wm * 64 + i * 16) * LDH + ks * 16, LDH);
#pragma unroll
            for (int j = 0; j < 4; j++)
                wmma::load_matrix_sync(fb[j], B + (wn * 64 + j * 16) * LDH + ks * 16, LDH);
#pragma unroll
            for (int i = 0; i < 4; i++)
#pragma unroll
                for (int j = 0; j < 4; j++)
                    wmma::mma_sync(acc[i][j], fa[i], fb[j], acc[i][j]);
        }
        __syncthreads();
        int kn = kc + NSTAGE;
        if (kn < NK && tid == 0) {
            mbar_expect_tx(mb0 + 8 * s, STAGE_BYTES);
            bulk_g2s(sb + s * STAGE_BYTES,              Asrc + (size_t)kn * 128 * LDH, TILE_BYTES, mb0 + 8 * s);
            bulk_g2s(sb + s * STAGE_BYTES + TILE_BYTES, Bsrc + (size_t)kn * 128 * LDH, TILE_BYTES, mb0 + 8 * s);
        }
    }

    // Stage fp32 (128 x 132), write partial (permuted order, no scatter).
    float* st = (float*)sh;
    __syncthreads();
#pragma unroll
    for (int i = 0; i < 4; i++)
#pragma unroll
        for (int j = 0; j < 4; j++)
            wmma::store_matrix_sync(st + (wm * 64 + i * 16) * LDST + wn * 64 + j * 16,
                                    acc[i][j], LDST, wmma::mem_row_major);
    __syncthreads();

    float* dst = g_gp + ((size_t)z * PADROWS + tile * 128) * DDIM + y * 128;
#pragma unroll
    for (int j = 0; j < 32; j++) {               // 128 rows x 32 float4 cols
        int p = tid + 128 * j;
        int r = p >> 5, c4 = (p & 31) * 4;
        *(float4*)(dst + (size_t)r * DDIM + c4) = *(float4*)&st[r * LDST + c4];
    }
}

// ---------------------------------------------------------------------------
// add partials + scatter to output
// ---------------------------------------------------------------------------
__global__ void add_kernel(float* __restrict__ out) {
    int idx = blockIdx.x * 256 + threadIdx.x;    // over PADROWS * 192 float4
    if (idx >= PADROWS * (DDIM / 4)) return;
    int p = idx / (DDIM / 4), c4 = (idx % (DDIM / 4)) * 4;
    int t = g_perm[p];
    if (t < 0) return;
    const float* a = g_gp + (size_t)p * DDIM + c4;
    const float* b = g_gp + (size_t)(PADROWS + p) * DDIM + c4;
    float4 va = *(const float4*)a, vb = *(const float4*)b;
    float4 o = make_float4(va.x + vb.x, va.y + vb.y, va.z + vb.z, va.w + vb.w);
    *(float4*)(out + (size_t)t * DDIM + c4) = o;
}

// ---------------------------------------------------------------------------
extern "C" void kernel_launch(void* const* d_in, const int* in_sizes, int n_in,
                              void* d_out, int out_size) {
    const float* x   = (const float*)d_in[0];
    const void*  pos = d_in[1];
    // d_in[2] = behavior_index: unused
    const float* gw  = (const float*)d_in[3];
    const float* uw  = (const float*)d_in[4];
    const float* dw  = (const float*)d_in[5];
    float* out = (float*)d_out;

    // Streams/events: created once (first call is the uncaptured correctness
    // run); every call issues the identical fork/join DAG -> deterministic.
    static cudaStream_t s2 = nullptr, s3 = nullptr;
    static cudaEvent_t eFork = nullptr, eWgu = nullptr, eWd = nullptr;
    if (!s2) {
        cudaStreamCreateWithFlags(&s2, cudaStreamNonBlocking);
        cudaStreamCreateWithFlags(&s3, cudaStreamNonBlocking);
        cudaEventCreateWithFlags(&eFork, cudaEventDisableTiming);
        cudaEventCreateWithFlags(&eWgu, cudaEventDisableTiming);
        cudaEventCreateWithFlags(&eWd, cudaEventDisableTiming);
        cudaFuncSetAttribute(gemm1_kernel, cudaFuncAttributeMaxDynamicSharedMemorySize, GSMEM);
        cudaFuncSetAttribute(gemm2_kernel, cudaFuncAttributeMaxDynamicSharedMemorySize, GSMEM);
    }

    // Fork: weight conversions run concurrently with routing + x conversion.
    cudaEventRecord(eFork, 0);
    cudaStreamWaitEvent(s2, eFork, 0);
    cudaStreamWaitEvent(s3, eFork, 0);

    cvt_wgu<<<(NEXP * 32 * 12 * 128 * 9 + 255) / 256, 256, 0, s2>>>(gw, uw);
    cudaEventRecord(eWgu, s2);
    cvt_wd <<<(NEXP * 6 * 32 * 128 * 9 + 255) / 256, 256, 0, s3>>>(dw);
    cudaEventRecord(eWd, s3);

    route_kernel<<<1, 256>>>(pos);
    cvt_x<<<(NTILES * 12 * 128 * 9 + 255) / 256, 256>>>(x);

    // gemm1 needs route+cvt_x (program order) + cvt_wgu (event join).
    cudaStreamWaitEvent(0, eWgu, 0);
    gemm1_kernel<<<dim3(NTILES, 32), 128, GSMEM>>>();

    // gemm2 needs gemm1 (program order) + cvt_wd (event join; hidden under gemm1).
    cudaStreamWaitEvent(0, eWd, 0);
    gemm2_kernel<<<dim3(NTILES, 6, 2), 128, GSMEM>>>();
    add_kernel<<<(PADROWS * (DDIM / 4) + 255) / 256, 256>>>(out);
}